// round 6
// baseline (speedup 1.0000x reference)
#include <cuda_runtime.h>
#include <cstdint>

#define NB      64
#define NN      8192
#define NSTATE  (NB * NN)        // 524288
#define NSTEPS  100
#define NSTEADY 50
#define NCHUNK  8
#define TN      256
#define NTILES  (NN / TN)        // 32
#define GATHER_BLOCKS (NCHUNK * NTILES)  // 256
#define ACC_PITCH 257            // 256 + 1 pad: conflict-free smem

// exp(-0.1/20), exp(-0.1/2) as float (rounded from double, matches np.exp -> float32)
#define EM 0.99501247919268232f
#define ES 0.95122942450071403f

#define SMEM_BYTES (64 * ACC_PITCH * 4 + 1024 * 8 + 1024 * 4)  // acc + smask + slist = 78080

// ---------------- device globals (scratch; no allocation in kernel_launch) --------------
__device__ float    g_Wt[(size_t)NN * NN];     // Wt[k][n] = W[n][k]   (256 MB)
__device__ float    g_volt[NSTATE];            // [k][b]
__device__ float    g_rec [NSTATE];
__device__ float    g_ff  [NSTATE];
__device__ float    g_sc  [NSTATE];
__device__ unsigned g_mask[NN * 2];            // per-neuron 64-bit batch spike mask (lo,hi)
__device__ float    g_part[NCHUNK][NSTATE];    // per-chunk matmul partial sums [n][b]

// ---------------- init: transpose state to [k][b], zero rec/sc --------------------------
__global__ void init_state_kernel(const float* __restrict__ volt0,
                                  const float* __restrict__ ff) {
    int t = blockIdx.x * 512 + threadIdx.x;    // t = b*NN + k (input layout)
    int b = t >> 13;
    int k = t & (NN - 1);
    int s = k * NB + b;
    g_volt[s] = volt0[t];
    g_ff[s]   = ff[t];
    g_rec[s]  = 0.0f;
    g_sc[s]   = 0.0f;
}

__global__ void zero_part_kernel() {
    int t = blockIdx.x * 512 + threadIdx.x;
    ((float*)g_part)[t] = 0.0f;
}

// ---------------- W transpose: Wt[k][n] = W[n][k] ---------------------------------------
__global__ void transpose_w_kernel(const float* __restrict__ W) {
    __shared__ float tile[32][33];
    int bx = blockIdx.x * 32;   // k base
    int by = blockIdx.y * 32;   // n base
    int tx = threadIdx.x, ty = threadIdx.y;
#pragma unroll
    for (int j = 0; j < 32; j += 8)
        tile[ty + j][tx] = W[(size_t)(by + ty + j) * NN + (bx + tx)];
    __syncthreads();
#pragma unroll
    for (int j = 0; j < 32; j += 8)
        g_Wt[(size_t)(bx + ty + j) * NN + (by + tx)] = tile[tx][ty + j];
}

// ---------------- per-step LIF update (fold previous step's matmul partials) ------------
__global__ void lif_step_kernel(int step) {
    int t = blockIdx.x * 512 + threadIdx.x;    // t = k*64 + b

    float ps = 0.0f;
#pragma unroll
    for (int c = 0; c < NCHUNK; c++) ps += g_part[c][t];

    // rec_s = ES * rec_{s-1} + 0.05 * (s_{s-1} @ Wt)   (zero at step 0: partials zeroed)
    float r = fmaf(ES, g_rec[t], 0.05f * ps);
    g_rec[t] = r;

    float net = g_ff[t] + r;
    float v   = fmaf(g_volt[t], EM, 0.1f * net);
    bool  sp  = (v >= 1.0f);
    g_volt[t] = sp ? 0.0f : v;
    if (sp && step >= NSTEADY) g_sc[t] += 1.0f;

    // warp = 32 consecutive batches of one neuron -> ballot gives half of 64-bit mask
    unsigned bal = __ballot_sync(0xffffffffu, sp);
    if ((threadIdx.x & 31) == 0) {
        int k    = t >> 6;
        int half = (t >> 5) & 1;
        g_mask[k * 2 + half] = bal;
    }
}

// ---------------- sparse gather: partial[c][n][b] = sum_{k in chunk c, spike(b,k)} Wt[k][n]
__global__ void __launch_bounds__(256, 2) gather_kernel() {
    extern __shared__ char smraw[];
    float* acc   = (float*)smraw;                                 // 64 * 257 floats
    uint2* smask = (uint2*)(smraw + 64 * ACC_PITCH * 4);          // 1024
    int*   slist = (int*)  (smraw + 64 * ACC_PITCH * 4 + 1024*8); // 1024
    __shared__ int warpcnt[8];
    __shared__ int warpoff[8];
    __shared__ int s_cnt;

    int tid  = threadIdx.x;
    int c    = blockIdx.x >> 5;          // 0..7 : handles k == c (mod 8)
    int n0   = (blockIdx.x & 31) * TN;   // n tile
    int lane = tid & 31, wid = tid >> 5;

    for (int i = tid; i < 64 * ACC_PITCH; i += 256) acc[i] = 0.0f;
    if (tid == 0) s_cnt = 0;
    __syncthreads();

    // deterministic ordered compaction of spiking k's in this chunk (k = c + 8*i)
    for (int r = 0; r < 4; r++) {
        int   i = r * 256 + tid;              // i in [0,1024)
        uint2 m = *(const uint2*)&g_mask[((i << 3) + c) * 2];
        bool  f = (m.x | m.y) != 0u;
        unsigned bal = __ballot_sync(0xffffffffu, f);
        if (lane == 0) warpcnt[wid] = __popc(bal);
        __syncthreads();
        if (tid == 0) {
            int s = s_cnt;
#pragma unroll
            for (int w = 0; w < 8; w++) { warpoff[w] = s; s += warpcnt[w]; }
            s_cnt = s;
        }
        __syncthreads();
        if (f) {
            int p = warpoff[wid] + __popc(bal & ((1u << lane) - 1u));
            slist[p] = i;
            smask[p] = m;
        }
        __syncthreads();
    }
    int cnt = s_cnt;

    // main gather loop, software-pipelined depth 2 for DRAM MLP
    const float* Wb = g_Wt + (size_t)c * NN + n0 + tid;   // row k=c, this thread's column
    float w0 = 0.0f, w1 = 0.0f;
    if (cnt > 0) w0 = Wb[(size_t)slist[0] * (8 * NN)];
    if (cnt > 1) w1 = Wb[(size_t)slist[1] * (8 * NN)];
    for (int j = 0; j < cnt; j++) {
        float w2 = (j + 2 < cnt) ? Wb[(size_t)slist[j + 2] * (8 * NN)] : 0.0f;
        uint2 mu = smask[j];
        unsigned long long m = (unsigned long long)mu.x |
                               ((unsigned long long)mu.y << 32);
        float w = w0;
        while (m) {
            int b = __ffsll((long long)m) - 1;
            acc[b * ACC_PITCH + tid] += w;    // thread-private smem column, no race
            m &= m - 1;
        }
        w0 = w1; w1 = w2;
    }
    __syncthreads();

    // coalesced writeback of partial tile [n][b]
    float* pout = ((float*)g_part) + (size_t)c * NSTATE + (size_t)n0 * NB;
    for (int idx = tid; idx < TN * NB; idx += 256) {
        int nl = idx >> 6, b = idx & 63;
        pout[idx] = acc[b * ACC_PITCH + nl];
    }
}

// ---------------- finalize: fold last partials into rec, transpose to [b][k], rates -----
__global__ void finalize_kernel(float* __restrict__ out) {
    int t = blockIdx.x * 512 + threadIdx.x;   // output index = b*NN + k
    int b = t >> 13;
    int k = t & (NN - 1);
    int s = k * NB + b;

    float ps = 0.0f;
#pragma unroll
    for (int c = 0; c < NCHUNK; c++) ps += g_part[c][s];

    out[t]              = g_volt[s];
    out[NSTATE + t]     = fmaf(ES, g_rec[s], 0.05f * ps);   // rec_100
    out[2 * NSTATE + t] = g_sc[s] / 50.0f;                  // rates
}

// ---------------- launch -----------------------------------------------------------------
extern "C" void kernel_launch(void* const* d_in, const int* in_sizes, int n_in,
                              void* d_out, int out_size) {
    const float* volt0 = (const float*)d_in[0];
    const float* W     = (const float*)d_in[1];
    const float* ff    = (const float*)d_in[2];

    // robust input identification by size (W is the only NN*NN tensor)
    {
        const float* st[2]; int c2 = 0;
        for (int i = 0; i < n_in; i++) {
            if (in_sizes[i] == NN * NN) W = (const float*)d_in[i];
            else if (in_sizes[i] == NSTATE && c2 < 2) st[c2++] = (const float*)d_in[i];
        }
        if (c2 == 2) { volt0 = st[0]; ff = st[1]; }
    }

    cudaFuncSetAttribute(gather_kernel,
                         cudaFuncAttributeMaxDynamicSharedMemorySize, SMEM_BYTES);

    init_state_kernel<<<NSTATE / 512, 512>>>(volt0, ff);
    zero_part_kernel<<<(NCHUNK * NSTATE) / 512, 512>>>();
    transpose_w_kernel<<<dim3(NN / 32, NN / 32), dim3(32, 8)>>>(W);

    for (int s = 0; s < NSTEPS; s++) {
        lif_step_kernel<<<NSTATE / 512, 512>>>(s);
        gather_kernel<<<GATHER_BLOCKS, 256, SMEM_BYTES>>>();
    }

    finalize_kernel<<<NSTATE / 512, 512>>>((float*)d_out);
}

// round 7
// speedup vs baseline: 2.3355x; 2.3355x over previous
#include <cuda_runtime.h>
#include <cstdint>

#define NB      64
#define NN      8192
#define NSTATE  (NB * NN)        // 524288
#define NSTEPS  100
#define NSTEADY 50
#define NCHUNK  8
#define TN      256
#define NTILES  (NN / TN)        // 32
#define GATHER_BLOCKS (NCHUNK * NTILES)  // 256
#define ACC_PITCH 257            // 256 + 1 pad: conflict-free smem
#define GD 8                     // prefetch group depth

// exp(-0.1/20), exp(-0.1/2) as float (rounded from double, matches np.exp -> float32)
#define EM 0.99501247919268232f
#define ES 0.95122942450071403f

#define SMEM_BYTES (64 * ACC_PITCH * 4 + 1024 * 8 + 1024 * 4)  // acc + smask + slist = 78080

// ---------------- device globals (scratch; no allocation in kernel_launch) --------------
__device__ float    g_Wt[(size_t)NN * NN];     // Wt[k][n] = W[n][k]   (256 MB)
__device__ float    g_volt[NSTATE];            // [k][b]
__device__ float    g_rec [NSTATE];
__device__ float    g_ff  [NSTATE];
__device__ float    g_sc  [NSTATE];
__device__ unsigned g_mask[NN * 2];            // per-neuron 64-bit batch spike mask (lo,hi)
__device__ float    g_part[NCHUNK][NSTATE];    // per-chunk matmul partial sums [n][b]

// ---------------- init: transpose state to [k][b], zero rec/sc --------------------------
__global__ void init_state_kernel(const float* __restrict__ volt0,
                                  const float* __restrict__ ff) {
    int t = blockIdx.x * 512 + threadIdx.x;    // t = b*NN + k (input layout)
    int b = t >> 13;
    int k = t & (NN - 1);
    int s = k * NB + b;
    g_volt[s] = volt0[t];
    g_ff[s]   = ff[t];
    g_rec[s]  = 0.0f;
    g_sc[s]   = 0.0f;
}

__global__ void zero_part_kernel() {
    int t = blockIdx.x * 512 + threadIdx.x;
    ((float*)g_part)[t] = 0.0f;
}

// ---------------- W transpose: Wt[k][n] = W[n][k] ---------------------------------------
__global__ void transpose_w_kernel(const float* __restrict__ W) {
    __shared__ float tile[32][33];
    int bx = blockIdx.x * 32;   // k base
    int by = blockIdx.y * 32;   // n base
    int tx = threadIdx.x, ty = threadIdx.y;
#pragma unroll
    for (int j = 0; j < 32; j += 8)
        tile[ty + j][tx] = W[(size_t)(by + ty + j) * NN + (bx + tx)];
    __syncthreads();
#pragma unroll
    for (int j = 0; j < 32; j += 8)
        g_Wt[(size_t)(bx + ty + j) * NN + (by + tx)] = tile[tx][ty + j];
}

// ---------------- per-step LIF update (fold previous step's matmul partials) ------------
__global__ void lif_step_kernel(int step) {
    int t = blockIdx.x * 512 + threadIdx.x;    // t = k*64 + b

    float ps = 0.0f;
#pragma unroll
    for (int c = 0; c < NCHUNK; c++) ps += g_part[c][t];

    // rec_s = ES * rec_{s-1} + 0.05 * (s_{s-1} @ Wt)   (zero at step 0: partials zeroed)
    float r = fmaf(ES, g_rec[t], 0.05f * ps);
    g_rec[t] = r;

    float net = g_ff[t] + r;
    float v   = fmaf(g_volt[t], EM, 0.1f * net);
    bool  sp  = (v >= 1.0f);
    g_volt[t] = sp ? 0.0f : v;
    if (sp && step >= NSTEADY) g_sc[t] += 1.0f;

    // warp = 32 consecutive batches of one neuron -> ballot gives half of 64-bit mask
    unsigned bal = __ballot_sync(0xffffffffu, sp);
    if ((threadIdx.x & 31) == 0) {
        int k    = t >> 6;
        int half = (t >> 5) & 1;
        g_mask[k * 2 + half] = bal;
    }
}

// ---------------- sparse gather: partial[c][n][b] = sum_{k in chunk c, spike(b,k)} Wt[k][n]
__global__ void __launch_bounds__(256, 2) gather_kernel() {
    extern __shared__ char smraw[];
    float* acc   = (float*)smraw;                                 // 64 * 257 floats
    uint2* smask = (uint2*)(smraw + 64 * ACC_PITCH * 4);          // 1024
    int*   slist = (int*)  (smraw + 64 * ACC_PITCH * 4 + 1024*8); // 1024
    __shared__ int warpcnt[8];
    __shared__ int warpoff[8];
    __shared__ int s_cnt;

    int tid  = threadIdx.x;
    int c    = blockIdx.x >> 5;          // 0..7 : handles k == c (mod 8)
    int n0   = (blockIdx.x & 31) * TN;   // n tile
    int lane = tid & 31, wid = tid >> 5;

    for (int i = tid; i < 64 * ACC_PITCH; i += 256) acc[i] = 0.0f;
    if (tid == 0) s_cnt = 0;
    __syncthreads();

    // deterministic ordered compaction of spiking k's in this chunk (k = c + 8*i)
    for (int r = 0; r < 4; r++) {
        int   i = r * 256 + tid;              // i in [0,1024)
        uint2 m = *(const uint2*)&g_mask[((i << 3) + c) * 2];
        bool  f = (m.x | m.y) != 0u;
        unsigned bal = __ballot_sync(0xffffffffu, f);
        if (lane == 0) warpcnt[wid] = __popc(bal);
        __syncthreads();
        if (tid == 0) {
            int s = s_cnt;
#pragma unroll
            for (int w = 0; w < 8; w++) { warpoff[w] = s; s += warpcnt[w]; }
            s_cnt = s;
        }
        __syncthreads();
        if (f) {
            int p = warpoff[wid] + __popc(bal & ((1u << lane) - 1u));
            slist[p] = i;
            smask[p] = m;
        }
        __syncthreads();
    }
    int cnt = s_cnt;

    // ---- main gather loop: depth-8 double-buffered prefetch (static reg indexing) ----
    const float* Wb = g_Wt + (size_t)c * NN + n0 + tid;   // row k=c, this thread's column

    float wA[GD], wB[GD];

#pragma unroll
    for (int p = 0; p < GD; p++)
        wA[p] = (p < cnt) ? Wb[(size_t)slist[p] * (8 * NN)] : 0.0f;

    for (int j0 = 0; j0 < cnt; j0 += 2 * GD) {
        // prefetch group B (j0+GD .. j0+2GD-1)
#pragma unroll
        for (int p = 0; p < GD; p++) {
            int j = j0 + GD + p;
            wB[p] = (j < cnt) ? Wb[(size_t)slist[j] * (8 * NN)] : 0.0f;
        }
        // process group A
#pragma unroll
        for (int p = 0; p < GD; p++) {
            int j = j0 + p;
            if (j < cnt) {
                uint2 mu = smask[j];
                unsigned long long m = (unsigned long long)mu.x |
                                       ((unsigned long long)mu.y << 32);
                float w = wA[p];
                while (m) {
                    int b = __ffsll((long long)m) - 1;
                    acc[b * ACC_PITCH + tid] += w;   // thread-private smem column
                    m &= m - 1;
                }
            }
        }
        // prefetch group A for next iteration (j0+2GD .. j0+3GD-1)
#pragma unroll
        for (int p = 0; p < GD; p++) {
            int j = j0 + 2 * GD + p;
            wA[p] = (j < cnt) ? Wb[(size_t)slist[j] * (8 * NN)] : 0.0f;
        }
        // process group B
#pragma unroll
        for (int p = 0; p < GD; p++) {
            int j = j0 + GD + p;
            if (j < cnt) {
                uint2 mu = smask[j];
                unsigned long long m = (unsigned long long)mu.x |
                                       ((unsigned long long)mu.y << 32);
                float w = wB[p];
                while (m) {
                    int b = __ffsll((long long)m) - 1;
                    acc[b * ACC_PITCH + tid] += w;
                    m &= m - 1;
                }
            }
        }
    }
    __syncthreads();

    // coalesced writeback of partial tile [n][b]
    float* pout = ((float*)g_part) + (size_t)c * NSTATE + (size_t)n0 * NB;
    for (int idx = tid; idx < TN * NB; idx += 256) {
        int nl = idx >> 6, b = idx & 63;
        pout[idx] = acc[b * ACC_PITCH + nl];
    }
}

// ---------------- finalize: fold last partials into rec, transpose to [b][k], rates -----
__global__ void finalize_kernel(float* __restrict__ out) {
    int t = blockIdx.x * 512 + threadIdx.x;   // output index = b*NN + k
    int b = t >> 13;
    int k = t & (NN - 1);
    int s = k * NB + b;

    float ps = 0.0f;
#pragma unroll
    for (int c = 0; c < NCHUNK; c++) ps += g_part[c][s];

    out[t]              = g_volt[s];
    out[NSTATE + t]     = fmaf(ES, g_rec[s], 0.05f * ps);   // rec_100
    out[2 * NSTATE + t] = g_sc[s] / 50.0f;                  // rates
}

// ---------------- launch -----------------------------------------------------------------
extern "C" void kernel_launch(void* const* d_in, const int* in_sizes, int n_in,
                              void* d_out, int out_size) {
    const float* volt0 = (const float*)d_in[0];
    const float* W     = (const float*)d_in[1];
    const float* ff    = (const float*)d_in[2];

    // robust input identification by size (W is the only NN*NN tensor)
    {
        const float* st[2]; int c2 = 0;
        for (int i = 0; i < n_in; i++) {
            if (in_sizes[i] == NN * NN) W = (const float*)d_in[i];
            else if (in_sizes[i] == NSTATE && c2 < 2) st[c2++] = (const float*)d_in[i];
        }
        if (c2 == 2) { volt0 = st[0]; ff = st[1]; }
    }

    cudaFuncSetAttribute(gather_kernel,
                         cudaFuncAttributeMaxDynamicSharedMemorySize, SMEM_BYTES);

    init_state_kernel<<<NSTATE / 512, 512>>>(volt0, ff);
    zero_part_kernel<<<(NCHUNK * NSTATE) / 512, 512>>>();
    transpose_w_kernel<<<dim3(NN / 32, NN / 32), dim3(32, 8)>>>(W);

    for (int s = 0; s < NSTEPS; s++) {
        lif_step_kernel<<<NSTATE / 512, 512>>>(s);
        gather_kernel<<<GATHER_BLOCKS, 256, SMEM_BYTES>>>();
    }

    finalize_kernel<<<NSTATE / 512, 512>>>((float*)d_out);
}

// round 8
// speedup vs baseline: 2.4673x; 1.0565x over previous
#include <cuda_runtime.h>
#include <cstdint>

#define NB      64
#define NN      8192
#define NSTATE  (NB * NN)        // 524288
#define NSTEPS  100
#define NSTEADY 50
#define NCHUNK  8
#define TN      256
#define NTILES  (NN / TN)        // 32
#define GATHER_BLOCKS (NCHUNK * NTILES)  // 256
#define ACC_PITCH 257            // 256 + 1 pad: conflict-free smem
#define GD 16                    // prefetch group depth (double-buffered => up to 32 in flight)

// exp(-0.1/20), exp(-0.1/2) as float (rounded from double, matches np.exp -> float32)
#define EM 0.99501247919268232f
#define ES 0.95122942450071403f

#define SMEM_BYTES (64 * ACC_PITCH * 4 + 1024 * 8 + 1024 * 4)  // acc + smask + slist = 78080

// ---------------- device globals (scratch; no allocation in kernel_launch) --------------
__device__ float    g_Wt[(size_t)NN * NN];     // Wt[k][n] = W[n][k]   (256 MB)
__device__ float    g_volt[NSTATE];            // [k][b]
__device__ float    g_rec [NSTATE];
__device__ float    g_ff  [NSTATE];
__device__ float    g_sc  [NSTATE];
__device__ unsigned g_mask[NN * 2];            // per-neuron 64-bit batch spike mask (lo,hi)
__device__ float    g_part[NCHUNK][NSTATE];    // per-chunk matmul partial sums [n][b]

// ---------------- init: transpose state to [k][b], zero rec/sc --------------------------
__global__ void init_state_kernel(const float* __restrict__ volt0,
                                  const float* __restrict__ ff) {
    int t = blockIdx.x * 512 + threadIdx.x;    // t = b*NN + k (input layout)
    int b = t >> 13;
    int k = t & (NN - 1);
    int s = k * NB + b;
    g_volt[s] = volt0[t];
    g_ff[s]   = ff[t];
    g_rec[s]  = 0.0f;
    g_sc[s]   = 0.0f;
}

__global__ void zero_part_kernel() {
    int t = blockIdx.x * 512 + threadIdx.x;
    ((float*)g_part)[t] = 0.0f;
}

// ---------------- W transpose: Wt[k][n] = W[n][k] ---------------------------------------
__global__ void transpose_w_kernel(const float* __restrict__ W) {
    __shared__ float tile[32][33];
    int bx = blockIdx.x * 32;   // k base
    int by = blockIdx.y * 32;   // n base
    int tx = threadIdx.x, ty = threadIdx.y;
#pragma unroll
    for (int j = 0; j < 32; j += 8)
        tile[ty + j][tx] = W[(size_t)(by + ty + j) * NN + (bx + tx)];
    __syncthreads();
#pragma unroll
    for (int j = 0; j < 32; j += 8)
        g_Wt[(size_t)(bx + ty + j) * NN + (by + tx)] = tile[tx][ty + j];
}

// ---------------- per-step LIF update (fold previous step's matmul partials) ------------
__global__ void lif_step_kernel(int step) {
    int t = blockIdx.x * 512 + threadIdx.x;    // t = k*64 + b

    float ps = 0.0f;
#pragma unroll
    for (int c = 0; c < NCHUNK; c++) ps += g_part[c][t];

    // rec_s = ES * rec_{s-1} + 0.05 * (s_{s-1} @ Wt)   (zero at step 0: partials zeroed)
    float r = fmaf(ES, g_rec[t], 0.05f * ps);
    g_rec[t] = r;

    float net = g_ff[t] + r;
    float v   = fmaf(g_volt[t], EM, 0.1f * net);
    bool  sp  = (v >= 1.0f);
    g_volt[t] = sp ? 0.0f : v;
    if (sp && step >= NSTEADY) g_sc[t] += 1.0f;

    // warp = 32 consecutive batches of one neuron -> ballot gives half of 64-bit mask
    unsigned bal = __ballot_sync(0xffffffffu, sp);
    if ((threadIdx.x & 31) == 0) {
        int k    = t >> 6;
        int half = (t >> 5) & 1;
        g_mask[k * 2 + half] = bal;
    }
}

// ---------------- sparse gather: partial[c][n][b] = sum_{k in chunk c, spike(b,k)} Wt[k][n]
__global__ void __launch_bounds__(256, 2) gather_kernel() {
    extern __shared__ char smraw[];
    float* acc   = (float*)smraw;                                 // 64 * 257 floats
    uint2* smask = (uint2*)(smraw + 64 * ACC_PITCH * 4);          // 1024
    int*   slist = (int*)  (smraw + 64 * ACC_PITCH * 4 + 1024*8); // 1024
    __shared__ int warpcnt[8];
    __shared__ int warpoff[8];
    __shared__ int s_cnt;

    int tid  = threadIdx.x;
    int c    = blockIdx.x >> 5;          // 0..7 : handles k == c (mod 8)
    int n0   = (blockIdx.x & 31) * TN;   // n tile
    int lane = tid & 31, wid = tid >> 5;

    for (int i = tid; i < 64 * ACC_PITCH; i += 256) acc[i] = 0.0f;
    if (tid == 0) s_cnt = 0;
    __syncthreads();

    // deterministic ordered compaction of spiking k's in this chunk (k = c + 8*i)
    for (int r = 0; r < 4; r++) {
        int   i = r * 256 + tid;              // i in [0,1024)
        uint2 m = *(const uint2*)&g_mask[((i << 3) + c) * 2];
        bool  f = (m.x | m.y) != 0u;
        unsigned bal = __ballot_sync(0xffffffffu, f);
        if (lane == 0) warpcnt[wid] = __popc(bal);
        __syncthreads();
        if (tid == 0) {
            int s = s_cnt;
#pragma unroll
            for (int w = 0; w < 8; w++) { warpoff[w] = s; s += warpcnt[w]; }
            s_cnt = s;
        }
        __syncthreads();
        if (f) {
            int p = warpoff[wid] + __popc(bal & ((1u << lane) - 1u));
            slist[p] = i;
            smask[p] = m;
        }
        __syncthreads();
    }
    int cnt = s_cnt;

    // ---- main gather loop: depth-16 double-buffered prefetch (static reg indexing) ----
    const float* Wb = g_Wt + (size_t)c * NN + n0 + tid;   // row k=c, this thread's column

    float wA[GD], wB[GD];

#pragma unroll
    for (int p = 0; p < GD; p++)
        wA[p] = (p < cnt) ? Wb[(size_t)slist[p] * (8 * NN)] : 0.0f;

    for (int j0 = 0; j0 < cnt; j0 += 2 * GD) {
        // prefetch group B (j0+GD .. j0+2GD-1)
#pragma unroll
        for (int p = 0; p < GD; p++) {
            int j = j0 + GD + p;
            wB[p] = (j < cnt) ? Wb[(size_t)slist[j] * (8 * NN)] : 0.0f;
        }
        // process group A
#pragma unroll
        for (int p = 0; p < GD; p++) {
            int j = j0 + p;
            if (j < cnt) {
                uint2 mu = smask[j];
                unsigned long long m = (unsigned long long)mu.x |
                                       ((unsigned long long)mu.y << 32);
                float w = wA[p];
                while (m) {
                    int b = __ffsll((long long)m) - 1;
                    acc[b * ACC_PITCH + tid] += w;   // thread-private smem column
                    m &= m - 1;
                }
            }
        }
        // prefetch group A for next iteration (j0+2GD .. j0+3GD-1)
#pragma unroll
        for (int p = 0; p < GD; p++) {
            int j = j0 + 2 * GD + p;
            wA[p] = (j < cnt) ? Wb[(size_t)slist[j] * (8 * NN)] : 0.0f;
        }
        // process group B
#pragma unroll
        for (int p = 0; p < GD; p++) {
            int j = j0 + GD + p;
            if (j < cnt) {
                uint2 mu = smask[j];
                unsigned long long m = (unsigned long long)mu.x |
                                       ((unsigned long long)mu.y << 32);
                float w = wB[p];
                while (m) {
                    int b = __ffsll((long long)m) - 1;
                    acc[b * ACC_PITCH + tid] += w;
                    m &= m - 1;
                }
            }
        }
    }
    __syncthreads();

    // coalesced writeback of partial tile [n][b]
    float* pout = ((float*)g_part) + (size_t)c * NSTATE + (size_t)n0 * NB;
    for (int idx = tid; idx < TN * NB; idx += 256) {
        int nl = idx >> 6, b = idx & 63;
        pout[idx] = acc[b * ACC_PITCH + nl];
    }
}

// ---------------- finalize: fold last partials into rec, transpose to [b][k], rates -----
__global__ void finalize_kernel(float* __restrict__ out) {
    int t = blockIdx.x * 512 + threadIdx.x;   // output index = b*NN + k
    int b = t >> 13;
    int k = t & (NN - 1);
    int s = k * NB + b;

    float ps = 0.0f;
#pragma unroll
    for (int c = 0; c < NCHUNK; c++) ps += g_part[c][s];

    out[t]              = g_volt[s];
    out[NSTATE + t]     = fmaf(ES, g_rec[s], 0.05f * ps);   // rec_100
    out[2 * NSTATE + t] = g_sc[s] / 50.0f;                  // rates
}

// ---------------- launch -----------------------------------------------------------------
extern "C" void kernel_launch(void* const* d_in, const int* in_sizes, int n_in,
                              void* d_out, int out_size) {
    const float* volt0 = (const float*)d_in[0];
    const float* W     = (const float*)d_in[1];
    const float* ff    = (const float*)d_in[2];

    // robust input identification by size (W is the only NN*NN tensor)
    {
        const float* st[2]; int c2 = 0;
        for (int i = 0; i < n_in; i++) {
            if (in_sizes[i] == NN * NN) W = (const float*)d_in[i];
            else if (in_sizes[i] == NSTATE && c2 < 2) st[c2++] = (const float*)d_in[i];
        }
        if (c2 == 2) { volt0 = st[0]; ff = st[1]; }
    }

    cudaFuncSetAttribute(gather_kernel,
                         cudaFuncAttributeMaxDynamicSharedMemorySize, SMEM_BYTES);

    init_state_kernel<<<NSTATE / 512, 512>>>(volt0, ff);
    zero_part_kernel<<<(NCHUNK * NSTATE) / 512, 512>>>();
    transpose_w_kernel<<<dim3(NN / 32, NN / 32), dim3(32, 8)>>>(W);

    for (int s = 0; s < NSTEPS; s++) {
        lif_step_kernel<<<NSTATE / 512, 512>>>(s);
        gather_kernel<<<GATHER_BLOCKS, 256, SMEM_BYTES>>>();
    }

    finalize_kernel<<<NSTATE / 512, 512>>>((float*)d_out);
}

// round 9
// speedup vs baseline: 2.4942x; 1.0109x over previous
#include <cuda_runtime.h>
#include <cstdint>

#define NB      64
#define NN      8192
#define NSTATE  (NB * NN)        // 524288
#define NSTEPS  100
#define NSTEADY 50
#define NCHUNK  8
#define TN      256
#define NTILES  (NN / TN)        // 32
#define GATHER_BLOCKS (NCHUNK * NTILES)  // 256
#define ACC_PITCH 257            // 256 + 1 pad: conflict-free smem
#define GD 16                    // prefetch group depth; 3 buffers => distance 32 j ahead

// exp(-0.1/20), exp(-0.1/2) as float (rounded from double, matches np.exp -> float32)
#define EM 0.99501247919268232f
#define ES 0.95122942450071403f

#define SMEM_BYTES (64 * ACC_PITCH * 4 + 1024 * 8 + 1024 * 4)  // acc + smask + slist = 78080

// ---------------- device globals (scratch; no allocation in kernel_launch) --------------
__device__ float    g_Wt[(size_t)NN * NN];     // Wt[k][n] = W[n][k]   (256 MB)
__device__ float    g_volt[NSTATE];            // [k][b]
__device__ float    g_rec [NSTATE];
__device__ float    g_ff  [NSTATE];
__device__ float    g_sc  [NSTATE];
__device__ unsigned g_mask[NN * 2];            // per-neuron 64-bit batch spike mask (lo,hi)
__device__ float    g_part[NCHUNK][NSTATE];    // per-chunk matmul partial sums [n][b]

// ---------------- init: transpose state to [k][b], zero rec/sc --------------------------
__global__ void init_state_kernel(const float* __restrict__ volt0,
                                  const float* __restrict__ ff) {
    int t = blockIdx.x * 512 + threadIdx.x;    // t = b*NN + k (input layout)
    int b = t >> 13;
    int k = t & (NN - 1);
    int s = k * NB + b;
    g_volt[s] = volt0[t];
    g_ff[s]   = ff[t];
    g_rec[s]  = 0.0f;
    g_sc[s]   = 0.0f;
}

__global__ void zero_part_kernel() {
    int t = blockIdx.x * 512 + threadIdx.x;
    ((float*)g_part)[t] = 0.0f;
}

// ---------------- W transpose: Wt[k][n] = W[n][k] ---------------------------------------
__global__ void transpose_w_kernel(const float* __restrict__ W) {
    __shared__ float tile[32][33];
    int bx = blockIdx.x * 32;   // k base
    int by = blockIdx.y * 32;   // n base
    int tx = threadIdx.x, ty = threadIdx.y;
#pragma unroll
    for (int j = 0; j < 32; j += 8)
        tile[ty + j][tx] = W[(size_t)(by + ty + j) * NN + (bx + tx)];
    __syncthreads();
#pragma unroll
    for (int j = 0; j < 32; j += 8)
        g_Wt[(size_t)(bx + ty + j) * NN + (by + tx)] = tile[tx][ty + j];
}

// ---------------- per-step LIF update (fold previous step's matmul partials) ------------
__global__ void lif_step_kernel(int step) {
    int t = blockIdx.x * 512 + threadIdx.x;    // t = k*64 + b

    float ps = 0.0f;
#pragma unroll
    for (int c = 0; c < NCHUNK; c++) ps += g_part[c][t];

    // rec_s = ES * rec_{s-1} + 0.05 * (s_{s-1} @ Wt)   (zero at step 0: partials zeroed)
    float r = fmaf(ES, g_rec[t], 0.05f * ps);
    g_rec[t] = r;

    float net = g_ff[t] + r;
    float v   = fmaf(g_volt[t], EM, 0.1f * net);
    bool  sp  = (v >= 1.0f);
    g_volt[t] = sp ? 0.0f : v;
    if (sp && step >= NSTEADY) g_sc[t] += 1.0f;

    // warp = 32 consecutive batches of one neuron -> ballot gives half of 64-bit mask
    unsigned bal = __ballot_sync(0xffffffffu, sp);
    if ((threadIdx.x & 31) == 0) {
        int k    = t >> 6;
        int half = (t >> 5) & 1;
        g_mask[k * 2 + half] = bal;
    }
}

// load one GD-wide group of weight values (guarded; static register indexing)
#define LOADG(buf, base)                                                     \
    _Pragma("unroll")                                                        \
    for (int p = 0; p < GD; p++) {                                           \
        int j = (base) + p;                                                  \
        buf[p] = (j < cnt) ? Wb[(size_t)slist[j] * (8 * NN)] : 0.0f;         \
    }

// scatter one GD-wide group into the smem accumulator (ascending j order)
#define PROCG(buf, base)                                                     \
    _Pragma("unroll")                                                        \
    for (int p = 0; p < GD; p++) {                                           \
        int j = (base) + p;                                                  \
        if (j < cnt) {                                                       \
            uint2 mu = smask[j];                                             \
            unsigned long long m = (unsigned long long)mu.x |                \
                                   ((unsigned long long)mu.y << 32);         \
            float w = buf[p];                                                \
            while (m) {                                                      \
                int b = __ffsll((long long)m) - 1;                           \
                acc[b * ACC_PITCH + tid] += w;                               \
                m &= m - 1;                                                  \
            }                                                                \
        }                                                                    \
    }

// ---------------- sparse gather: partial[c][n][b] = sum_{k in chunk c, spike(b,k)} Wt[k][n]
__global__ void __launch_bounds__(256, 2) gather_kernel() {
    extern __shared__ char smraw[];
    float* acc   = (float*)smraw;                                 // 64 * 257 floats
    uint2* smask = (uint2*)(smraw + 64 * ACC_PITCH * 4);          // 1024
    int*   slist = (int*)  (smraw + 64 * ACC_PITCH * 4 + 1024*8); // 1024
    __shared__ int warpcnt[8];
    __shared__ int warpoff[8];
    __shared__ int s_cnt;

    int tid  = threadIdx.x;
    int c    = blockIdx.x >> 5;          // 0..7 : handles k == c (mod 8)
    int n0   = (blockIdx.x & 31) * TN;   // n tile
    int lane = tid & 31, wid = tid >> 5;

    for (int i = tid; i < 64 * ACC_PITCH; i += 256) acc[i] = 0.0f;
    if (tid == 0) s_cnt = 0;
    __syncthreads();

    // deterministic ordered compaction of spiking k's in this chunk (k = c + 8*i)
    for (int r = 0; r < 4; r++) {
        int   i = r * 256 + tid;              // i in [0,1024)
        uint2 m = *(const uint2*)&g_mask[((i << 3) + c) * 2];
        bool  f = (m.x | m.y) != 0u;
        unsigned bal = __ballot_sync(0xffffffffu, f);
        if (lane == 0) warpcnt[wid] = __popc(bal);
        __syncthreads();
        if (tid == 0) {
            int s = s_cnt;
#pragma unroll
            for (int w = 0; w < 8; w++) { warpoff[w] = s; s += warpcnt[w]; }
            s_cnt = s;
        }
        __syncthreads();
        if (f) {
            int p = warpoff[wid] + __popc(bal & ((1u << lane) - 1u));
            slist[p] = i;
            smask[p] = m;
        }
        __syncthreads();
    }
    int cnt = s_cnt;

    // ---- main gather: triple-buffered ring, prefetch distance = 2 groups (32 j) ----
    const float* Wb = g_Wt + (size_t)c * NN + n0 + tid;   // row k=c, this thread's column

    float w0[GD], w1[GD], w2[GD];

    LOADG(w0, 0)
    LOADG(w1, GD)

    for (int j0 = 0; j0 < cnt; j0 += 3 * GD) {
        LOADG(w2, j0 + 2 * GD)
        PROCG(w0, j0)
        LOADG(w0, j0 + 3 * GD)
        PROCG(w1, j0 + GD)
        LOADG(w1, j0 + 4 * GD)
        PROCG(w2, j0 + 2 * GD)
    }
    __syncthreads();

    // coalesced writeback of partial tile [n][b]
    float* pout = ((float*)g_part) + (size_t)c * NSTATE + (size_t)n0 * NB;
    for (int idx = tid; idx < TN * NB; idx += 256) {
        int nl = idx >> 6, b = idx & 63;
        pout[idx] = acc[b * ACC_PITCH + nl];
    }
}

// ---------------- finalize: fold last partials into rec, transpose to [b][k], rates -----
__global__ void finalize_kernel(float* __restrict__ out) {
    int t = blockIdx.x * 512 + threadIdx.x;   // output index = b*NN + k
    int b = t >> 13;
    int k = t & (NN - 1);
    int s = k * NB + b;

    float ps = 0.0f;
#pragma unroll
    for (int c = 0; c < NCHUNK; c++) ps += g_part[c][s];

    out[t]              = g_volt[s];
    out[NSTATE + t]     = fmaf(ES, g_rec[s], 0.05f * ps);   // rec_100
    out[2 * NSTATE + t] = g_sc[s] / 50.0f;                  // rates
}

// ---------------- launch -----------------------------------------------------------------
extern "C" void kernel_launch(void* const* d_in, const int* in_sizes, int n_in,
                              void* d_out, int out_size) {
    const float* volt0 = (const float*)d_in[0];
    const float* W     = (const float*)d_in[1];
    const float* ff    = (const float*)d_in[2];

    // robust input identification by size (W is the only NN*NN tensor)
    {
        const float* st[2]; int c2 = 0;
        for (int i = 0; i < n_in; i++) {
            if (in_sizes[i] == NN * NN) W = (const float*)d_in[i];
            else if (in_sizes[i] == NSTATE && c2 < 2) st[c2++] = (const float*)d_in[i];
        }
        if (c2 == 2) { volt0 = st[0]; ff = st[1]; }
    }

    cudaFuncSetAttribute(gather_kernel,
                         cudaFuncAttributeMaxDynamicSharedMemorySize, SMEM_BYTES);

    init_state_kernel<<<NSTATE / 512, 512>>>(volt0, ff);
    zero_part_kernel<<<(NCHUNK * NSTATE) / 512, 512>>>();
    transpose_w_kernel<<<dim3(NN / 32, NN / 32), dim3(32, 8)>>>(W);

    for (int s = 0; s < NSTEPS; s++) {
        lif_step_kernel<<<NSTATE / 512, 512>>>(s);
        gather_kernel<<<GATHER_BLOCKS, 256, SMEM_BYTES>>>();
    }

    finalize_kernel<<<NSTATE / 512, 512>>>((float*)d_out);
}